// round 1
// baseline (speedup 1.0000x reference)
#include <cuda_runtime.h>

#define Sx 2048
#define Bx 2
#define Ex 512
#define Hx 8
#define Ix 64
#define Mx 2048
#define Kx 4096          // M + S
#define QKV3 1536
#define FFx 2048
#define ROWS (Sx*Bx)     // 4096
#define KB_ (Kx*Bx)      // 8192
#define KSTR 68          // padded stride (16B aligned, conflict-reducing)
#define EPSF 1e-5f

// ---------------- scratch (static device arrays: no allocation) -------------
__device__ float g_qkv[(size_t)KB_ * QKV3];     // 50.3 MB
__device__ float g_r[(size_t)Kx * Ex];          // 8 MB
__device__ float g_attn[(size_t)ROWS * Ex];     // 8 MB
__device__ float g_tmp[(size_t)ROWS * Ex];      // 8 MB
__device__ float g_attnout[(size_t)ROWS * Ex];  // 8 MB
__device__ float g_ff1[(size_t)ROWS * FFx];     // 32 MB
__device__ float g_ff2[(size_t)ROWS * Ex];      // 8 MB

// ---------------- SGEMM: C(MxN) = A(MxK) * B(KxN), 128x128x8 tiles ----------
// EPI: 0=none, 1=+bias, 2=+bias+relu.  SPLITA: A rows gather from two tensors.
template<int EPI, bool SPLITA>
__global__ __launch_bounds__(256, 2) void sgemm128(
    const float* __restrict__ A0, const float* __restrict__ A1, int splitRow,
    const float* __restrict__ Bm, const float* __restrict__ bias,
    float* __restrict__ C, int Md, int Nd, int Kd)
{
    __shared__ __align__(16) float As[8][128];
    __shared__ __align__(16) float Bs[8][128];
    int tid = threadIdx.x;
    int tx = tid & 15, ty = tid >> 4;
    int bm = blockIdx.y * 128, bn = blockIdx.x * 128;
    int arow = tid >> 1, acol = (tid & 1) * 4;   // A tile load: 128 rows x 8 cols
    int brow = tid >> 5, bcol = (tid & 31) * 4;  // B tile load: 8 rows x 128 cols

    const float* Ap;
    {
        int grow = bm + arow;
        if (SPLITA && grow >= splitRow) Ap = A1 + (size_t)(grow - splitRow) * Kd;
        else                            Ap = A0 + (size_t)grow * Kd;
    }

    float acc[8][8];
#pragma unroll
    for (int i = 0; i < 8; i++)
#pragma unroll
        for (int j = 0; j < 8; j++) acc[i][j] = 0.f;

    for (int k0 = 0; k0 < Kd; k0 += 8) {
        float4 av = *(const float4*)(Ap + k0 + acol);
        As[acol + 0][arow] = av.x;
        As[acol + 1][arow] = av.y;
        As[acol + 2][arow] = av.z;
        As[acol + 3][arow] = av.w;
        *(float4*)&Bs[brow][bcol] =
            *(const float4*)(Bm + (size_t)(k0 + brow) * Nd + bn + bcol);
        __syncthreads();
#pragma unroll
        for (int kk = 0; kk < 8; kk++) {
            float4 a0 = *(const float4*)&As[kk][ty * 8];
            float4 a1 = *(const float4*)&As[kk][ty * 8 + 4];
            float4 b0 = *(const float4*)&Bs[kk][tx * 8];
            float4 b1 = *(const float4*)&Bs[kk][tx * 8 + 4];
            float af[8] = {a0.x, a0.y, a0.z, a0.w, a1.x, a1.y, a1.z, a1.w};
            float bf[8] = {b0.x, b0.y, b0.z, b0.w, b1.x, b1.y, b1.z, b1.w};
#pragma unroll
            for (int i = 0; i < 8; i++)
#pragma unroll
                for (int j = 0; j < 8; j++)
                    acc[i][j] += af[i] * bf[j];
        }
        __syncthreads();
    }

#pragma unroll
    for (int i = 0; i < 8; i++) {
        size_t row = (size_t)(bm + ty * 8 + i);
#pragma unroll
        for (int j = 0; j < 8; j += 4) {
            int col = bn + tx * 8 + j;
            float4 vo;
            vo.x = acc[i][j + 0]; vo.y = acc[i][j + 1];
            vo.z = acc[i][j + 2]; vo.w = acc[i][j + 3];
            if (EPI >= 1) {
                vo.x += bias[col + 0]; vo.y += bias[col + 1];
                vo.z += bias[col + 2]; vo.w += bias[col + 3];
            }
            if (EPI == 2) {
                vo.x = fmaxf(vo.x, 0.f); vo.y = fmaxf(vo.y, 0.f);
                vo.z = fmaxf(vo.z, 0.f); vo.w = fmaxf(vo.w, 0.f);
            }
            *(float4*)(C + row * Nd + col) = vo;
        }
    }
}

// ---------------- Flash attention with Transformer-XL relative shift --------
// score[s,k] = ((q+u)[s]·kk[k] + (q+v)[s]·r[k + S-1-s]) * 0.125, mask k > s+M.
// Per CTA: 64 queries for one (b,h). Key loop: AC GEMM 64x64x64 + BD band GEMM
// 64x128x64 (r rows jlo..jlo+127), combine on diagonal, online softmax, P·V.
__global__ __launch_bounds__(256, 1) void flash_kernel(
    const float* __restrict__ qkv, const float* __restrict__ rbuf,
    const float* __restrict__ u, const float* __restrict__ v,
    float* __restrict__ attn)
{
    extern __shared__ __align__(16) float sm[];
    float* Qu   = sm;                    // 64*64
    float* Qv   = Qu + 64 * 64;          // 64*64
    float* Ksh  = Qv + 64 * 64;          // 64*KSTR
    float* Vsh  = Ksh + 64 * KSTR;       // 64*KSTR
    float* Rsh  = Vsh + 64 * KSTR;       // 128*KSTR
    float* BDsh = Rsh + 128 * KSTR;      // 64*128 (also reused as P)

    int tid = threadIdx.x;
    int tx = tid & 15, ty = tid >> 4;
    int qt = (gridDim.x - 1) - blockIdx.x;  // heavy tiles scheduled first
    int b = blockIdx.y >> 3, h = blockIdx.y & 7;
    int s0 = qt * 64;
    int hoff = h * 64;

    for (int idx = tid; idx < 64 * 64; idx += 256) {
        int sR = idx >> 6, i = idx & 63;
        float qval = qkv[((size_t)(Mx + s0 + sR) * Bx + b) * QKV3 + hoff + i];
        Qu[sR * 64 + i] = qval + u[hoff + i];
        Qv[sR * 64 + i] = qval + v[hoff + i];
    }

    float m_r[4], l_r[4], O[4][4];
#pragma unroll
    for (int a = 0; a < 4; a++) {
        m_r[a] = -1e30f; l_r[a] = 0.f;
#pragma unroll
        for (int c = 0; c < 4; c++) O[a][c] = 0.f;
    }

    int nkt = s0 / 64 + Mx / 64 + 1;
    for (int kt = 0; kt < nkt; kt++) {
        int k0 = kt * 64;
        __syncthreads();   // smem reuse fence (covers Qu/Qv init on kt==0)
        for (int idx = tid; idx < 64 * 64; idx += 256) {
            int kr = idx >> 6, i = idx & 63;
            size_t base = ((size_t)(k0 + kr) * Bx + b) * QKV3 + hoff + i;
            Ksh[kr * KSTR + i] = qkv[base + 512];
            Vsh[kr * KSTR + i] = qkv[base + 1024];
        }
        int jlo = k0 + (Sx - 1) - s0 - 63;   // >= 0 always
        for (int idx = tid; idx < 128 * 64; idx += 256) {
            int d = idx >> 6, i = idx & 63;
            int j = jlo + d;
            if (j > Kx - 1) j = Kx - 1;      // only masked entries touch this
            Rsh[d * KSTR + i] = rbuf[(size_t)j * Ex + hoff + i];
        }
        __syncthreads();

        // AC GEMM: 4x4 per thread
        float ac[4][4];
#pragma unroll
        for (int a = 0; a < 4; a++)
#pragma unroll
            for (int c = 0; c < 4; c++) ac[a][c] = 0.f;
        for (int i = 0; i < 64; i += 4) {
            float4 qa[4], kb[4];
#pragma unroll
            for (int a = 0; a < 4; a++)
                qa[a] = *(const float4*)&Qu[(ty * 4 + a) * 64 + i];
#pragma unroll
            for (int c = 0; c < 4; c++)
                kb[c] = *(const float4*)&Ksh[(tx * 4 + c) * KSTR + i];
#pragma unroll
            for (int a = 0; a < 4; a++)
#pragma unroll
                for (int c = 0; c < 4; c++)
                    ac[a][c] += qa[a].x * kb[c].x + qa[a].y * kb[c].y
                              + qa[a].z * kb[c].z + qa[a].w * kb[c].w;
        }

        // BD band GEMM: 4x8 per thread over 128 diagonal-band columns
        float bd[4][8];
#pragma unroll
        for (int a = 0; a < 4; a++)
#pragma unroll
            for (int c = 0; c < 8; c++) bd[a][c] = 0.f;
        for (int i = 0; i < 64; i += 4) {
            float4 qa[4];
#pragma unroll
            for (int a = 0; a < 4; a++)
                qa[a] = *(const float4*)&Qv[(ty * 4 + a) * 64 + i];
            float4 rb[8];
#pragma unroll
            for (int c = 0; c < 8; c++)
                rb[c] = *(const float4*)&Rsh[(tx * 8 + c) * KSTR + i];
#pragma unroll
            for (int a = 0; a < 4; a++)
#pragma unroll
                for (int c = 0; c < 8; c++)
                    bd[a][c] += qa[a].x * rb[c].x + qa[a].y * rb[c].y
                              + qa[a].z * rb[c].z + qa[a].w * rb[c].w;
        }
#pragma unroll
        for (int a = 0; a < 4; a++)
#pragma unroll
            for (int c = 0; c < 8; c++)
                BDsh[(ty * 4 + a) * 128 + tx * 8 + c] = bd[a][c];
        __syncthreads();

        // combine along rel-shift diagonal + mask
        float sc[4][4];
#pragma unroll
        for (int a = 0; a < 4; a++) {
            int sR = ty * 4 + a;
#pragma unroll
            for (int c = 0; c < 4; c++) {
                int kc = tx * 4 + c;
                float val = (ac[a][c] + BDsh[sR * 128 + (kc - sR + 63)]) * 0.125f;
                if (k0 + kc > s0 + sR + Mx) val = -1e30f;
                sc[a][c] = val;
            }
        }
        __syncthreads();   // all BD reads done before P overwrites buffer

        // online softmax (row reduce over 16 lanes sharing ty)
#pragma unroll
        for (int a = 0; a < 4; a++) {
            float mx = fmaxf(fmaxf(sc[a][0], sc[a][1]), fmaxf(sc[a][2], sc[a][3]));
#pragma unroll
            for (int off = 8; off; off >>= 1)
                mx = fmaxf(mx, __shfl_xor_sync(0xffffffffu, mx, off));
            float mnew = fmaxf(m_r[a], mx);
            float corr = __expf(m_r[a] - mnew);
            float rs = 0.f;
#pragma unroll
            for (int c = 0; c < 4; c++) {
                float p = __expf(sc[a][c] - mnew);
                sc[a][c] = p; rs += p;
            }
#pragma unroll
            for (int off = 8; off; off >>= 1)
                rs += __shfl_xor_sync(0xffffffffu, rs, off);
            l_r[a] = l_r[a] * corr + rs;
            m_r[a] = mnew;
#pragma unroll
            for (int c = 0; c < 4; c++) O[a][c] *= corr;
            int sR = ty * 4 + a;
#pragma unroll
            for (int c = 0; c < 4; c++)
                BDsh[sR * 128 + tx * 4 + c] = sc[a][c];
        }
        __syncthreads();

        // P·V accumulate
        for (int i = 0; i < 64; i += 4) {
            float4 pa[4];
#pragma unroll
            for (int a = 0; a < 4; a++)
                pa[a] = *(const float4*)&BDsh[(ty * 4 + a) * 128 + i];
            float4 vb[4];
#pragma unroll
            for (int t = 0; t < 4; t++)
                vb[t] = *(const float4*)&Vsh[(i + t) * KSTR + tx * 4];
            const float* vbp = (const float*)vb;
#pragma unroll
            for (int a = 0; a < 4; a++)
#pragma unroll
                for (int c = 0; c < 4; c++)
                    O[a][c] += pa[a].x * vbp[0 * 4 + c] + pa[a].y * vbp[1 * 4 + c]
                             + pa[a].z * vbp[2 * 4 + c] + pa[a].w * vbp[3 * 4 + c];
        }
    }

#pragma unroll
    for (int a = 0; a < 4; a++) {
        int sg = s0 + ty * 4 + a;
        float inv = 1.0f / l_r[a];
#pragma unroll
        for (int c = 0; c < 4; c++)
            attn[((size_t)sg * Bx + b) * Ex + hoff + tx * 4 + c] = O[a][c] * inv;
    }
}

// ---------------- LayerNorm(X + Y) over last dim 512 ------------------------
__global__ void ln_add_kernel(const float* __restrict__ X, const float* __restrict__ Y,
                              const float* __restrict__ g, const float* __restrict__ bb,
                              float* __restrict__ out)
{
    __shared__ float red[4];
    int row = blockIdx.x;
    int tid = threadIdx.x;   // 128 threads, 4 floats each
    const float4* X4 = (const float4*)(X + (size_t)row * Ex);
    const float4* Y4 = (const float4*)(Y + (size_t)row * Ex);
    float4 x = X4[tid], y = Y4[tid];
    float4 vv = {x.x + y.x, x.y + y.y, x.z + y.z, x.w + y.w};
    float s = vv.x + vv.y + vv.z + vv.w;
#pragma unroll
    for (int off = 16; off; off >>= 1) s += __shfl_xor_sync(0xffffffffu, s, off);
    if ((tid & 31) == 0) red[tid >> 5] = s;
    __syncthreads();
    float mu = (red[0] + red[1] + red[2] + red[3]) * (1.f / 512.f);
    float d0 = vv.x - mu, d1 = vv.y - mu, d2 = vv.z - mu, d3 = vv.w - mu;
    float q = d0 * d0 + d1 * d1 + d2 * d2 + d3 * d3;
    __syncthreads();
#pragma unroll
    for (int off = 16; off; off >>= 1) q += __shfl_xor_sync(0xffffffffu, q, off);
    if ((tid & 31) == 0) red[tid >> 5] = q;
    __syncthreads();
    float var = (red[0] + red[1] + red[2] + red[3]) * (1.f / 512.f);
    float rs = rsqrtf(var + EPSF);
    const float4* g4 = (const float4*)g;
    const float4* b4 = (const float4*)bb;
    float4 gg = g4[tid], bv = b4[tid];
    float4 o;
    o.x = d0 * rs * gg.x + bv.x;
    o.y = d1 * rs * gg.y + bv.y;
    o.z = d2 * rs * gg.z + bv.z;
    o.w = d3 * rs * gg.w + bv.w;
    ((float4*)(out + (size_t)row * Ex))[tid] = o;
}

// ---------------------------------------------------------------------------
#define FLASH_SMEM ((2*64*64 + 2*64*KSTR + 128*KSTR + 64*128) * 4)

extern "C" void kernel_launch(void* const* d_in, const int* in_sizes, int n_in,
                              void* d_out, int out_size)
{
    const float* inputDec = (const float*)d_in[0];
    const float* posEmb   = (const float*)d_in[1];
    const float* u        = (const float*)d_in[2];
    const float* v        = (const float*)d_in[3];
    const float* memories = (const float*)d_in[4];
    const float* Wqkv     = (const float*)d_in[5];
    const float* Wr       = (const float*)d_in[6];
    const float* Wo       = (const float*)d_in[7];
    const float* ln1_g    = (const float*)d_in[8];
    const float* ln1_b    = (const float*)d_in[9];
    const float* W1       = (const float*)d_in[10];
    const float* b1       = (const float*)d_in[11];
    const float* W2       = (const float*)d_in[12];
    const float* b2       = (const float*)d_in[13];
    const float* ln2_g    = (const float*)d_in[14];
    const float* ln2_b    = (const float*)d_in[15];
    float* out = (float*)d_out;

    float *qkv, *rb, *attn, *tmp, *attnout, *ff1, *ff2;
    cudaGetSymbolAddress((void**)&qkv,     g_qkv);
    cudaGetSymbolAddress((void**)&rb,      g_r);
    cudaGetSymbolAddress((void**)&attn,    g_attn);
    cudaGetSymbolAddress((void**)&tmp,     g_tmp);
    cudaGetSymbolAddress((void**)&attnout, g_attnout);
    cudaGetSymbolAddress((void**)&ff1,     g_ff1);
    cudaGetSymbolAddress((void**)&ff2,     g_ff2);

    cudaFuncSetAttribute(flash_kernel,
                         cudaFuncAttributeMaxDynamicSharedMemorySize, FLASH_SMEM);

    // 1) qkv = concat(memories, inputDec) @ Wqkv
    sgemm128<0, true><<<dim3(QKV3 / 128, KB_ / 128), 256>>>(
        memories, inputDec, Mx * Bx, Wqkv, nullptr, qkv, KB_, QKV3, Ex);
    // 2) r = posEmbeddings @ Wr
    sgemm128<0, false><<<dim3(Ex / 128, Kx / 128), 256>>>(
        posEmb, nullptr, 0, Wr, nullptr, rb, Kx, Ex, Ex);
    // 3) fused rel-pos flash attention
    flash_kernel<<<dim3(Sx / 64, Bx * Hx), 256, FLASH_SMEM>>>(qkv, rb, u, v, attn);
    // 4) attn @ Wo
    sgemm128<0, false><<<dim3(Ex / 128, ROWS / 128), 256>>>(
        attn, nullptr, 0, Wo, nullptr, tmp, ROWS, Ex, Ex);
    // 5) attn_out = LN(inputDec + attnWo)
    ln_add_kernel<<<ROWS, 128>>>(inputDec, tmp, ln1_g, ln1_b, attnout);
    // 6) ff1 = relu(attn_out @ W1 + b1)
    sgemm128<2, false><<<dim3(FFx / 128, ROWS / 128), 256>>>(
        attnout, nullptr, 0, W1, b1, ff1, ROWS, FFx, Ex);
    // 7) ff2 = ff1 @ W2 + b2
    sgemm128<1, false><<<dim3(Ex / 128, ROWS / 128), 256>>>(
        ff1, nullptr, 0, W2, b2, ff2, ROWS, Ex, FFx);
    // 8) out = LN(attn_out + ff2)
    ln_add_kernel<<<ROWS, 128>>>(attnout, ff2, ln2_g, ln2_b, out);
}